// round 11
// baseline (speedup 1.0000x reference)
#include <cuda_runtime.h>
#include <cuda_bf16.h>
#include <cuda_fp8.h>
#include <stdint.h>

typedef __nv_bfloat16 bf16;
typedef unsigned char u8;

#define B_   2
#define L_   2048
#define D_   2048
#define NH_  16
#define HD_  128

// ---------------- scratch (device globals) ----------------
__device__ __align__(128) u8   g_Xq8 [B_ * L_ * D_];
__device__ __align__(128) u8   g_Xkv8[B_ * L_ * D_];
__device__ __align__(128) u8   g_W8  [4][D_ * D_];
__device__ __align__(128) bf16 g_Q   [B_ * L_ * D_];
__device__ __align__(128) bf16 g_K   [B_ * L_ * D_];
__device__ __align__(128) u8   g_V8  [B_ * L_ * D_];
__device__ __align__(128) u8   g_Vt8 [B_ * NH_ * HD_ * L_];
__device__ __align__(128) bf16 g_S   [(size_t)B_ * NH_ * L_ * L_];
__device__ __align__(128) u8   g_P8  [(size_t)B_ * NH_ * L_ * L_];
__device__ __align__(128) u8   g_AO8 [B_ * L_ * D_];

// ---------------- numerics ----------------
__device__ __forceinline__ u8 e4m3b(float x) {
    return (u8)__nv_cvt_float_to_fp8(x, __NV_SATFINITE, __NV_E4M3);
}

// ---------------- async copy / ldmatrix / mma ----------------
__device__ __forceinline__ uint32_t smem_u32(const void* p) {
    uint32_t a;
    asm("{ .reg .u64 t; cvta.to.shared.u64 t, %1; cvt.u32.u64 %0, t; }" : "=r"(a) : "l"(p));
    return a;
}
__device__ __forceinline__ void cp16(uint32_t s, const void* g) {
    asm volatile("cp.async.cg.shared.global [%0], [%1], 16;\n" :: "r"(s), "l"(g) : "memory");
}
__device__ __forceinline__ void cp_commit() { asm volatile("cp.async.commit_group;\n" ::: "memory"); }
template <int N>
__device__ __forceinline__ void cp_wait() { asm volatile("cp.async.wait_group %0;\n" :: "n"(N) : "memory"); }
__device__ __forceinline__ void ldm_x4(uint32_t* r, uint32_t a) {
    asm volatile("ldmatrix.sync.aligned.m8n8.x4.shared.b16 {%0,%1,%2,%3}, [%4];"
                 : "=r"(r[0]), "=r"(r[1]), "=r"(r[2]), "=r"(r[3]) : "r"(a));
}
__device__ __forceinline__ void mma_bf16(float* c, const uint32_t* a, const uint32_t* b) {
    asm volatile(
        "mma.sync.aligned.m16n8k16.row.col.f32.bf16.bf16.f32 "
        "{%0,%1,%2,%3}, {%4,%5,%6,%7}, {%8,%9}, {%0,%1,%2,%3};\n"
        : "+f"(c[0]), "+f"(c[1]), "+f"(c[2]), "+f"(c[3])
        : "r"(a[0]), "r"(a[1]), "r"(a[2]), "r"(a[3]), "r"(b[0]), "r"(b[1]));
}
__device__ __forceinline__ void mma_fp8(float* c, const uint32_t* a, const uint32_t* b) {
    asm volatile(
        "mma.sync.aligned.m16n8k32.row.col.f32.e4m3.e4m3.f32 "
        "{%0,%1,%2,%3}, {%4,%5,%6,%7}, {%8,%9}, {%0,%1,%2,%3};\n"
        : "+f"(c[0]), "+f"(c[1]), "+f"(c[2]), "+f"(c[3])
        : "r"(a[0]), "r"(a[1]), "r"(a[2]), "r"(a[3]), "r"(b[0]), "r"(b[1]));
}

// ---------------- fused elementwise kernels ----------------
__global__ __launch_bounds__(256) void k_quant2(const float* __restrict__ in0,
                                                const float* __restrict__ in1,
                                                u8* __restrict__ o0, u8* __restrict__ o1, int n) {
    const float* in = blockIdx.y ? in1 : in0;
    u8* out = blockIdx.y ? o1 : o0;
    int i = (blockIdx.x * 256 + threadIdx.x) * 4;
    if (i >= n) return;
    float4 v = *(const float4*)(in + i);
    uint32_t w = (uint32_t)e4m3b(v.x) | ((uint32_t)e4m3b(v.y) << 8)
               | ((uint32_t)e4m3b(v.z) << 16) | ((uint32_t)e4m3b(v.w) << 24);
    *(uint32_t*)(out + i) = w;
}

__global__ __launch_bounds__(256) void k_qtrans4(const float* __restrict__ W0,
                                                 const float* __restrict__ W1,
                                                 const float* __restrict__ W2,
                                                 const float* __restrict__ W3,
                                                 u8* __restrict__ Wt) {
    __shared__ float t[32][33];
    int zz = blockIdx.z;
    const float* W = (zz == 0) ? W0 : (zz == 1) ? W1 : (zz == 2) ? W2 : W3;
    u8* dst = Wt + (size_t)zz * D_ * D_;
    int n0 = blockIdx.x * 32, k0 = blockIdx.y * 32;
    int tx = threadIdx.x, ty0 = threadIdx.y;
#pragma unroll
    for (int j = 0; j < 4; j++) {
        int ty = ty0 + j * 8;
        t[ty][tx] = W[(size_t)(k0 + ty) * D_ + n0 + tx];
    }
    __syncthreads();
#pragma unroll
    for (int j = 0; j < 4; j++) {
        int ty = ty0 + j * 8;
        dst[(size_t)(n0 + ty) * D_ + k0 + tx] = e4m3b(t[tx][ty]);
    }
}

__global__ __launch_bounds__(256) void k_vtrans8() {
    __shared__ u8 t[32][36];
    int z = blockIdx.z; int b = z / NH_, n = z % NH_;
    int kk0 = blockIdx.x * 32, h0 = blockIdx.y * 32;
    int tx = threadIdx.x, ty0 = threadIdx.y;
#pragma unroll
    for (int j = 0; j < 4; j++) {
        int ty = ty0 + j * 8;
        t[ty][tx] = g_V8[(size_t)(b * L_ + kk0 + ty) * D_ + n * HD_ + h0 + tx];
    }
    __syncthreads();
#pragma unroll
    for (int j = 0; j < 4; j++) {
        int ty = ty0 + j * 8;
        g_Vt8[((size_t)(b * NH_ + n) * HD_ + h0 + ty) * L_ + kk0 + tx] = t[tx][ty];
    }
}

// ================= GEMM config (R6 proven-best): CTA 256x128, 8 warps 64x64, BK=128B =================
#define STRD  144               // 128B K-slab + 16B pad
#define ASTG  (256 * STRD)      // 36864 B
#define BSTG  (128 * STRD)      // 18432 B
#define PSTG  (ASTG + BSTG)     // 55296 B per stage
#define NSTG  3

// ---- shared mainloop body; expands at FUNCTION scope so `acc` is visible to the epilogue ----
#define GEMM_CORE(MMA_STMT)                                                            \
    uint32_t sbase = smem_u32(dsm);                                                    \
    int lr = lane & 7, h8 = (lane >> 3) & 1, q = lane >> 4;                            \
    uint32_t aoff = (uint32_t)((wm * 64 + h8 * 8 + lr) * STRD + q * 16);               \
    uint32_t boff = (uint32_t)((wn * 64 + q * 8 + lr) * STRD + h8 * 16);               \
    float acc[4][8][4];                                                                \
    _Pragma("unroll") for (int i = 0; i < 4; i++)                                      \
    _Pragma("unroll") for (int j = 0; j < 8; j++)                                      \
    _Pragma("unroll") for (int p = 0; p < 4; p++) acc[i][j][p] = 0.f;                  \
    int nK = Kb / 128;                                                                 \
    int r8 = tid >> 3, c8 = (tid & 7) * 16;                                            \
    auto load_stage = [&](int stg, int kt) {                                           \
        const u8* Ag = A + (size_t)kt * 128;                                           \
        const u8* Bg = B + (size_t)kt * 128;                                           \
        uint32_t sa = sbase + stg * PSTG;                                              \
        uint32_t sb = sa + ASTG;                                                       \
        _Pragma("unroll") for (int i = 0; i < 8; i++) {                                \
            int rr = r8 + i * 32;                                                      \
            cp16(sa + rr * STRD + c8, Ag + (size_t)rr * ldab + c8);                    \
        }                                                                              \
        _Pragma("unroll") for (int i = 0; i < 4; i++) {                                \
            int rr = r8 + i * 32;                                                      \
            cp16(sb + rr * STRD + c8, Bg + (size_t)rr * ldbb + c8);                    \
        }                                                                              \
        cp_commit();                                                                   \
    };                                                                                 \
    load_stage(0, 0);                                                                  \
    if (nK > 1) load_stage(1, 1); else cp_commit();                                    \
    uint32_t af[2][4][4], bfr[2][8][2];                                                \
    auto load_frags = [&](int buf, uint32_t sa, uint32_t sb, uint32_t k0) {            \
        _Pragma("unroll") for (int mi = 0; mi < 4; mi++)                               \
            ldm_x4(af[buf][mi], sa + aoff + mi * (16 * STRD) + k0);                    \
        _Pragma("unroll") for (int nj = 0; nj < 4; nj++) {                             \
            uint32_t qd[4];                                                            \
            ldm_x4(qd, sb + boff + nj * (16 * STRD) + k0);                             \
            bfr[buf][2 * nj][0] = qd[0]; bfr[buf][2 * nj][1] = qd[1];                  \
            bfr[buf][2 * nj + 1][0] = qd[2]; bfr[buf][2 * nj + 1][1] = qd[3];          \
        }                                                                              \
    };                                                                                 \
    for (int kt = 0; kt < nK; kt++) {                                                  \
        cp_wait<1>();                                                                  \
        __syncthreads();                                                               \
        if (kt + 2 < nK) load_stage((kt + 2) % NSTG, kt + 2);                          \
        else cp_commit();                                                              \
        uint32_t sa = sbase + (kt % NSTG) * PSTG;                                      \
        uint32_t sb = sa + ASTG;                                                       \
        load_frags(0, sa, sb, 0);                                                      \
        _Pragma("unroll") for (int kk = 0; kk < 4; kk++) {                             \
            int cur = kk & 1;                                                          \
            if (kk < 3) load_frags(cur ^ 1, sa, sb, (kk + 1) * 32);                    \
            _Pragma("unroll") for (int mi = 0; mi < 4; mi++)                           \
            _Pragma("unroll") for (int ni = 0; ni < 8; ni++) { MMA_STMT; }             \
        }                                                                              \
    }

// MODE: 0 bf16 out, 1 bf16(bf16(acc)*bf16(scale)), 2 e4m3 byte out, 3 f32 out.
template <int MODE, bool FP8>
__global__ __launch_bounds__(256, 1) void k_mm(
    const u8* __restrict__ A, const u8* __restrict__ B, void* __restrict__ Cout,
    int Kb, int ldab, int ldbb, int ldc,
    long long sAb, long long sAn, long long sBb, long long sBn,
    long long sCb, long long sCn, int nh)
{
    extern __shared__ __align__(16) u8 dsm[];

    int z = blockIdx.z;
    int bb = z / nh, hh = z % nh;
    A += (size_t)bb * sAb + (size_t)hh * sAn + (size_t)blockIdx.y * 256 * ldab;
    B += (size_t)bb * sBb + (size_t)hh * sBn + (size_t)blockIdx.x * 128 * ldbb;
    size_t cofs = (size_t)bb * sCb + (size_t)hh * sCn + (size_t)blockIdx.y * 256 * ldc
                  + (size_t)blockIdx.x * 128;

    int tid = threadIdx.x;
    int warp = tid >> 5, lane = tid & 31;
    int wm = warp >> 1, wn = warp & 1;
    int g = tid % 32 >> 2, t4 = lane & 3;

    // single expansion at function scope; dead branch folds at compile time
    GEMM_CORE(
        if (FP8) mma_fp8(acc[mi][ni], af[cur][mi], bfr[cur][ni]);
        else     mma_bf16(acc[mi][ni], af[cur][mi], bfr[cur][ni]);
    );

    const float sc = __bfloat162float(__float2bfloat16(0.08838834764831845f));
#pragma unroll
    for (int mi = 0; mi < 4; mi++) {
#pragma unroll
        for (int ni = 0; ni < 8; ni++) {
            int row = wm * 64 + mi * 16 + g;
            int col = wn * 64 + ni * 8 + t4 * 2;
            size_t o0 = cofs + (size_t)row * ldc + col;
            size_t o1 = o0 + (size_t)8 * ldc;
            float a0 = acc[mi][ni][0], a1 = acc[mi][ni][1];
            float a2 = acc[mi][ni][2], a3 = acc[mi][ni][3];
            if (MODE == 0) {
                bf16* Cb = (bf16*)Cout;
                __nv_bfloat162 v0, v1;
                v0.x = __float2bfloat16(a0); v0.y = __float2bfloat16(a1);
                v1.x = __float2bfloat16(a2); v1.y = __float2bfloat16(a3);
                *(__nv_bfloat162*)(Cb + o0) = v0;
                *(__nv_bfloat162*)(Cb + o1) = v1;
            } else if (MODE == 1) {
                bf16* Cb = (bf16*)Cout;
                __nv_bfloat162 v0, v1;
                v0.x = __float2bfloat16(__bfloat162float(__float2bfloat16(a0)) * sc);
                v0.y = __float2bfloat16(__bfloat162float(__float2bfloat16(a1)) * sc);
                v1.x = __float2bfloat16(__bfloat162float(__float2bfloat16(a2)) * sc);
                v1.y = __float2bfloat16(__bfloat162float(__float2bfloat16(a3)) * sc);
                *(__nv_bfloat162*)(Cb + o0) = v0;
                *(__nv_bfloat162*)(Cb + o1) = v1;
            } else if (MODE == 2) {
                u8* C8 = (u8*)Cout;
                uint16_t w0 = (uint16_t)e4m3b(__bfloat162float(__float2bfloat16(a0)))
                            | ((uint16_t)e4m3b(__bfloat162float(__float2bfloat16(a1))) << 8);
                uint16_t w1 = (uint16_t)e4m3b(__bfloat162float(__float2bfloat16(a2)))
                            | ((uint16_t)e4m3b(__bfloat162float(__float2bfloat16(a3))) << 8);
                *(uint16_t*)(C8 + o0) = w0;
                *(uint16_t*)(C8 + o1) = w1;
            } else {
                float* Cf = (float*)Cout;
                float2 v0, v1;
                v0.x = __bfloat162float(__float2bfloat16(a0));
                v0.y = __bfloat162float(__float2bfloat16(a1));
                v1.x = __bfloat162float(__float2bfloat16(a2));
                v1.y = __bfloat162float(__float2bfloat16(a3));
                *(float2*)(Cf + o0) = v0;
                *(float2*)(Cf + o1) = v1;
            }
        }
    }
}

// ================= merged Q/K/V projection: grid (16, 16, 3), ONE launch = 768 CTAs =================
// z = 0: Q = Xq8 x W0 (bf16 out), z = 1: K = Xkv8 x W1 (bf16 out), z = 2: V = Xkv8 x W2 (e4m3 out)
__global__ __launch_bounds__(256, 1) void k_proj3() {
    extern __shared__ __align__(16) u8 dsm[];

    int zz = blockIdx.z;
    const u8* A = (zz == 0) ? g_Xq8 : g_Xkv8;
    const u8* B = g_W8[zz];
    A += (size_t)blockIdx.y * 256 * D_;
    B += (size_t)blockIdx.x * 128 * D_;
    size_t cofs = (size_t)blockIdx.y * 256 * D_ + (size_t)blockIdx.x * 128;
    int Kb = D_, ldab = D_, ldbb = D_;

    int tid = threadIdx.x;
    int warp = tid >> 5, lane = tid & 31;
    int wm = warp >> 1, wn = warp & 1;
    int g = lane >> 2, t4 = lane & 3;

    GEMM_CORE(mma_fp8(acc[mi][ni], af[cur][mi], bfr[cur][ni]));

#pragma unroll
    for (int mi = 0; mi < 4; mi++) {
#pragma unroll
        for (int ni = 0; ni < 8; ni++) {
            int row = wm * 64 + mi * 16 + g;
            int col = wn * 64 + ni * 8 + t4 * 2;
            size_t o0 = cofs + (size_t)row * D_ + col;
            size_t o1 = o0 + (size_t)8 * D_;
            float a0 = acc[mi][ni][0], a1 = acc[mi][ni][1];
            float a2 = acc[mi][ni][2], a3 = acc[mi][ni][3];
            if (zz < 2) {
                bf16* Cb = zz ? g_K : g_Q;
                __nv_bfloat162 v0, v1;
                v0.x = __float2bfloat16(a0); v0.y = __float2bfloat16(a1);
                v1.x = __float2bfloat16(a2); v1.y = __float2bfloat16(a3);
                *(__nv_bfloat162*)(Cb + o0) = v0;
                *(__nv_bfloat162*)(Cb + o1) = v1;
            } else {
                uint16_t w0 = (uint16_t)e4m3b(__bfloat162float(__float2bfloat16(a0)))
                            | ((uint16_t)e4m3b(__bfloat162float(__float2bfloat16(a1))) << 8);
                uint16_t w1 = (uint16_t)e4m3b(__bfloat162float(__float2bfloat16(a2)))
                            | ((uint16_t)e4m3b(__bfloat162float(__float2bfloat16(a3))) << 8);
                *(uint16_t*)(g_V8 + o0) = w0;
                *(uint16_t*)(g_V8 + o1) = w1;
            }
        }
    }
}

// ---------------- softmax: bf16 logits -> e4m3 P bytes ----------------
__global__ __launch_bounds__(256) void k_softmax() {
    __shared__ float red[8];
    size_t row = blockIdx.x;
    const bf16* p = g_S + row * (size_t)L_;
    u8* po = g_P8 + row * (size_t)L_;
    int tid = threadIdx.x, lane = tid & 31, w = tid >> 5;

    union { uint4 u; bf16 b[8]; } U;
    U.u = *(const uint4*)(p + tid * 8);
    float v[8];
#pragma unroll
    for (int j = 0; j < 8; j++) v[j] = __bfloat162float(U.b[j]);

    float m = v[0];
#pragma unroll
    for (int j = 1; j < 8; j++) m = fmaxf(m, v[j]);
#pragma unroll
    for (int s = 16; s > 0; s >>= 1) m = fmaxf(m, __shfl_xor_sync(0xffffffffu, m, s));
    if (lane == 0) red[w] = m;
    __syncthreads();
    float mv = fmaxf(fmaxf(fmaxf(red[0], red[1]), fmaxf(red[2], red[3])),
                     fmaxf(fmaxf(red[4], red[5]), fmaxf(red[6], red[7])));

    float sum = 0.f;
#pragma unroll
    for (int j = 0; j < 8; j++) { v[j] = expf(v[j] - mv); sum += v[j]; }
#pragma unroll
    for (int s = 16; s > 0; s >>= 1) sum += __shfl_xor_sync(0xffffffffu, sum, s);
    __syncthreads();
    if (lane == 0) red[w] = sum;
    __syncthreads();
    float tot = red[0] + red[1] + red[2] + red[3] + red[4] + red[5] + red[6] + red[7];

    union { uint2 u; u8 b[8]; } O;
#pragma unroll
    for (int j = 0; j < 8; j++) {
        float pj = v[j] / tot;
        bf16 hb = __float2bfloat16(pj);
        O.b[j] = e4m3b(__bfloat162float(hb));
    }
    *(uint2*)(po + tid * 8) = O.u;
}

// ---------------- launch ----------------
extern "C" void kernel_launch(void* const* d_in, const int* in_sizes, int n_in,
                              void* d_out, int out_size) {
    const float* inq  = (const float*)d_in[0];
    const float* inkv = (const float*)d_in[1];
    const float* Wq   = (const float*)d_in[2];
    const float* Wk   = (const float*)d_in[3];
    const float* Wv   = (const float*)d_in[4];
    const float* Wo   = (const float*)d_in[5];
    float* out = (float*)d_out;

    u8 *pXq8, *pXkv8, *pW8, *pVt8, *pP8, *pAO8;
    bf16 *pQ, *pK, *pS;
    cudaGetSymbolAddress((void**)&pXq8,  g_Xq8);
    cudaGetSymbolAddress((void**)&pXkv8, g_Xkv8);
    cudaGetSymbolAddress((void**)&pW8,   g_W8);
    cudaGetSymbolAddress((void**)&pQ,    g_Q);
    cudaGetSymbolAddress((void**)&pK,    g_K);
    cudaGetSymbolAddress((void**)&pVt8,  g_Vt8);
    cudaGetSymbolAddress((void**)&pS,    g_S);
    cudaGetSymbolAddress((void**)&pP8,   g_P8);
    cudaGetSymbolAddress((void**)&pAO8,  g_AO8);
    u8* pW3 = pW8 + 3 * (size_t)D_ * D_;

    const int SMEM = NSTG * PSTG;   // 165888
    cudaFuncSetAttribute(k_proj3,        cudaFuncAttributeMaxDynamicSharedMemorySize, SMEM);
    cudaFuncSetAttribute(k_mm<1, false>, cudaFuncAttributeMaxDynamicSharedMemorySize, SMEM);
    cudaFuncSetAttribute(k_mm<2, true>,  cudaFuncAttributeMaxDynamicSharedMemorySize, SMEM);
    cudaFuncSetAttribute(k_mm<3, true>,  cudaFuncAttributeMaxDynamicSharedMemorySize, SMEM);

    const int n = B_ * L_ * D_;
    dim3 tb(32, 8);

    // idx 0: all 4 weight quant+transpose
    k_qtrans4<<<dim3(64, 64, 4), tb>>>(Wq, Wk, Wv, Wo, pW8);
    // idx 1: both input quants
    k_quant2<<<dim3(n / 4 / 256, 2), 256>>>(inq, inkv, pXq8, pXkv8, n);
    // idx 2: merged Q/K/V projections — 768 CTAs, one launch
    k_proj3<<<dim3(D_ / 128, (B_ * L_) / 256, 3), 256, SMEM>>>();
    // idx 3: S = (Q K^T)*scale per head  (global idx 5 -> ncu profiles THIS)
    k_mm<1, false><<<dim3(L_ / 128, L_ / 256, B_ * NH_), 256, SMEM>>>(
        (const u8*)pQ, (const u8*)pK, pS, HD_ * 2, D_ * 2, D_ * 2, L_,
        (long long)L_ * D_ * 2, HD_ * 2, (long long)L_ * D_ * 2, HD_ * 2,
        (long long)NH_ * L_ * L_, (long long)L_ * L_, NH_);
    // idx 4: V transpose per head
    k_vtrans8<<<dim3(L_ / 32, HD_ / 32, B_ * NH_), tb>>>();
    // idx 5: softmax -> e4m3 P
    k_softmax<<<B_ * NH_ * L_, 256>>>();
    // idx 6: O = P @ V per head (fp8)
    k_mm<2, true><<<dim3(HD_ / 128, L_ / 256, B_ * NH_), 256, SMEM>>>(
        pP8, pVt8, pAO8, L_, L_, L_, D_,
        (long long)NH_ * L_ * L_, (long long)L_ * L_,
        (long long)NH_ * HD_ * L_, (long long)HD_ * L_,
        (long long)L_ * D_, HD_, NH_);
    // idx 7: final projection, f32 store
    k_mm<3, true><<<dim3(D_ / 128, (B_ * L_) / 256, 1), 256, SMEM>>>(
        pAO8, pW3, out, D_, D_, D_, D_, 0, 0, 0, 0, 0, 0, 1);
}

// round 15
// speedup vs baseline: 1.5002x; 1.5002x over previous
#include <cuda_runtime.h>
#include <cuda_bf16.h>
#include <cuda_fp8.h>
#include <stdint.h>

typedef __nv_bfloat16 bf16;
typedef unsigned char u8;

#define B_   2
#define L_   2048
#define D_   2048
#define NH_  16
#define HD_  128
#define NTOK (B_ * L_ * D_)

// ---------------- scratch (device globals) ----------------
__device__ __align__(128) u8   g_X3  [3][NTOK];        // e4m3 inputs: q, kv, kv
__device__ __align__(128) u8   g_W8  [4][D_ * D_];     // e4m3 W^T
__device__ __align__(128) bf16 g_QKV [3][NTOK];        // Q, K, V projections (bf16)
__device__ __align__(128) u8   g_Vt8 [B_ * NH_ * HD_ * L_];
__device__ __align__(128) bf16 g_S   [(size_t)B_ * NH_ * L_ * L_];
__device__ __align__(128) u8   g_P8  [(size_t)B_ * NH_ * L_ * L_];
__device__ __align__(128) u8   g_AO8 [B_ * L_ * D_];

// ---------------- numerics ----------------
__device__ __forceinline__ u8 e4m3b(float x) {
    return (u8)__nv_cvt_float_to_fp8(x, __NV_SATFINITE, __NV_E4M3);
}

// ---------------- async copy / ldmatrix / mma ----------------
__device__ __forceinline__ uint32_t smem_u32(const void* p) {
    uint32_t a;
    asm("{ .reg .u64 t; cvta.to.shared.u64 t, %1; cvt.u32.u64 %0, t; }" : "=r"(a) : "l"(p));
    return a;
}
__device__ __forceinline__ void cp16(uint32_t s, const void* g) {
    asm volatile("cp.async.cg.shared.global [%0], [%1], 16;\n" :: "r"(s), "l"(g) : "memory");
}
__device__ __forceinline__ void cp_commit() { asm volatile("cp.async.commit_group;\n" ::: "memory"); }
template <int N>
__device__ __forceinline__ void cp_wait() { asm volatile("cp.async.wait_group %0;\n" :: "n"(N) : "memory"); }
__device__ __forceinline__ void ldm_x4(uint32_t* r, uint32_t a) {
    asm volatile("ldmatrix.sync.aligned.m8n8.x4.shared.b16 {%0,%1,%2,%3}, [%4];"
                 : "=r"(r[0]), "=r"(r[1]), "=r"(r[2]), "=r"(r[3]) : "r"(a));
}
__device__ __forceinline__ void mma_bf16(float* c, const uint32_t* a, const uint32_t* b) {
    asm volatile(
        "mma.sync.aligned.m16n8k16.row.col.f32.bf16.bf16.f32 "
        "{%0,%1,%2,%3}, {%4,%5,%6,%7}, {%8,%9}, {%0,%1,%2,%3};\n"
        : "+f"(c[0]), "+f"(c[1]), "+f"(c[2]), "+f"(c[3])
        : "r"(a[0]), "r"(a[1]), "r"(a[2]), "r"(a[3]), "r"(b[0]), "r"(b[1]));
}
__device__ __forceinline__ void mma_fp8(float* c, const uint32_t* a, const uint32_t* b) {
    asm volatile(
        "mma.sync.aligned.m16n8k32.row.col.f32.e4m3.e4m3.f32 "
        "{%0,%1,%2,%3}, {%4,%5,%6,%7}, {%8,%9}, {%0,%1,%2,%3};\n"
        : "+f"(c[0]), "+f"(c[1]), "+f"(c[2]), "+f"(c[3])
        : "r"(a[0]), "r"(a[1]), "r"(a[2]), "r"(a[3]), "r"(b[0]), "r"(b[1]));
}

// ---------------- fused elementwise kernels ----------------
// y = 0: quant(inputs_q) -> slot0; y = 1: quant(inputs_kv) -> slot1; y = 2: same -> slot2
__global__ __launch_bounds__(256) void k_quant3(const float* __restrict__ in0,
                                                const float* __restrict__ in1, int n) {
    const float* in = (blockIdx.y == 0) ? in0 : in1;
    u8* out = g_X3[blockIdx.y];
    int i = (blockIdx.x * 256 + threadIdx.x) * 4;
    if (i >= n) return;
    float4 v = *(const float4*)(in + i);
    uint32_t w = (uint32_t)e4m3b(v.x) | ((uint32_t)e4m3b(v.y) << 8)
               | ((uint32_t)e4m3b(v.z) << 16) | ((uint32_t)e4m3b(v.w) << 24);
    *(uint32_t*)(out + i) = w;
}

__global__ __launch_bounds__(256) void k_qtrans4(const float* __restrict__ W0,
                                                 const float* __restrict__ W1,
                                                 const float* __restrict__ W2,
                                                 const float* __restrict__ W3,
                                                 u8* __restrict__ Wt) {
    __shared__ float t[32][33];
    int zz = blockIdx.z;
    const float* W = (zz == 0) ? W0 : (zz == 1) ? W1 : (zz == 2) ? W2 : W3;
    u8* dst = Wt + (size_t)zz * D_ * D_;
    int n0 = blockIdx.x * 32, k0 = blockIdx.y * 32;
    int tx = threadIdx.x, ty0 = threadIdx.y;
#pragma unroll
    for (int j = 0; j < 4; j++) {
        int ty = ty0 + j * 8;
        t[ty][tx] = W[(size_t)(k0 + ty) * D_ + n0 + tx];
    }
    __syncthreads();
#pragma unroll
    for (int j = 0; j < 4; j++) {
        int ty = ty0 + j * 8;
        dst[(size_t)(n0 + ty) * D_ + k0 + tx] = e4m3b(t[tx][ty]);
    }
}

// V transpose per head: read bf16 V (slot2), requantize to e4m3 byte, write transposed.
__global__ __launch_bounds__(256) void k_vtrans8() {
    __shared__ u8 t[32][36];
    int z = blockIdx.z; int b = z / NH_, n = z % NH_;
    int kk0 = blockIdx.x * 32, h0 = blockIdx.y * 32;
    int tx = threadIdx.x, ty0 = threadIdx.y;
#pragma unroll
    for (int j = 0; j < 4; j++) {
        int ty = ty0 + j * 8;
        bf16 v = g_QKV[2][(size_t)(b * L_ + kk0 + ty) * D_ + n * HD_ + h0 + tx];
        t[ty][tx] = e4m3b(__bfloat162float(v));
    }
    __syncthreads();
#pragma unroll
    for (int j = 0; j < 4; j++) {
        int ty = ty0 + j * 8;
        g_Vt8[((size_t)(b * NH_ + n) * HD_ + h0 + ty) * L_ + kk0 + tx] = t[tx][ty];
    }
}

// ================= unified byte-addressed NT GEMM (R7 proven-best, verbatim) =================
// CTA 256x128, 8 warps (4m x 2n) 64x64 warp tiles, BK=128B, 3-stage ring, frag double-buffer.
// MODE: 0 bf16 out, 1 scaled-bf16 out, 2 e4m3 byte out, 3 f32 out.
#define STRD  144
#define ASTG  (256 * STRD)
#define BSTG  (128 * STRD)
#define PSTG  (ASTG + BSTG)
#define NSTG  3

template <int MODE, bool FP8>
__global__ __launch_bounds__(256, 1) void k_mm(
    const u8* __restrict__ A, const u8* __restrict__ B, void* __restrict__ Cout,
    int Kb, int ldab, int ldbb, int ldc,
    long long sAb, long long sAn, long long sBb, long long sBn,
    long long sCb, long long sCn, int nh)
{
    extern __shared__ __align__(16) u8 dsm[];

    int z = blockIdx.z;
    int bb = z / nh, hh = z % nh;
    A += (size_t)bb * sAb + (size_t)hh * sAn + (size_t)blockIdx.y * 256 * ldab;
    B += (size_t)bb * sBb + (size_t)hh * sBn + (size_t)blockIdx.x * 128 * ldbb;
    size_t cofs = (size_t)bb * sCb + (size_t)hh * sCn + (size_t)blockIdx.y * 256 * ldc
                  + (size_t)blockIdx.x * 128;

    int tid = threadIdx.x;
    int warp = tid >> 5, lane = tid & 31;
    int wm = warp >> 1, wn = warp & 1;       // 4x2 warps, warp tile 64x64
    int g = lane >> 2, t4 = lane & 3;

    uint32_t sbase = smem_u32(dsm);
    int lr = lane & 7, h8 = (lane >> 3) & 1, q = lane >> 4;
    uint32_t aoff = (uint32_t)((wm * 64 + h8 * 8 + lr) * STRD + q * 16);
    uint32_t boff = (uint32_t)((wn * 64 + q * 8 + lr) * STRD + h8 * 16);

    float acc[4][8][4];
#pragma unroll
    for (int i = 0; i < 4; i++)
#pragma unroll
        for (int j = 0; j < 8; j++)
#pragma unroll
            for (int p = 0; p < 4; p++) acc[i][j][p] = 0.f;

    int nK = Kb / 128;
    int r8 = tid >> 3, c8 = (tid & 7) * 16;

    auto load_stage = [&](int stg, int kt) {
        const u8* Ag = A + (size_t)kt * 128;
        const u8* Bg = B + (size_t)kt * 128;
        uint32_t sa = sbase + stg * PSTG;
        uint32_t sb = sa + ASTG;
#pragma unroll
        for (int i = 0; i < 8; i++) {
            int rr = r8 + i * 32;
            cp16(sa + rr * STRD + c8, Ag + (size_t)rr * ldab + c8);
        }
#pragma unroll
        for (int i = 0; i < 4; i++) {
            int rr = r8 + i * 32;
            cp16(sb + rr * STRD + c8, Bg + (size_t)rr * ldbb + c8);
        }
        cp_commit();
    };

    load_stage(0, 0);
    if (nK > 1) load_stage(1, 1); else cp_commit();

    uint32_t af[2][4][4], bfr[2][8][2];

    auto load_frags = [&](int buf, uint32_t sa, uint32_t sb, uint32_t k0) {
#pragma unroll
        for (int mi = 0; mi < 4; mi++)
            ldm_x4(af[buf][mi], sa + aoff + mi * (16 * STRD) + k0);
#pragma unroll
        for (int nj = 0; nj < 4; nj++) {
            uint32_t qd[4];
            ldm_x4(qd, sb + boff + nj * (16 * STRD) + k0);
            bfr[buf][2 * nj][0] = qd[0]; bfr[buf][2 * nj][1] = qd[1];
            bfr[buf][2 * nj + 1][0] = qd[2]; bfr[buf][2 * nj + 1][1] = qd[3];
        }
    };

    for (int kt = 0; kt < nK; kt++) {
        cp_wait<1>();
        __syncthreads();
        if (kt + 2 < nK) load_stage((kt + 2) % NSTG, kt + 2);
        else cp_commit();

        uint32_t sa = sbase + (kt % NSTG) * PSTG;
        uint32_t sb = sa + ASTG;

        load_frags(0, sa, sb, 0);
#pragma unroll
        for (int kk = 0; kk < 4; kk++) {
            int cur = kk & 1;
            if (kk < 3) load_frags(cur ^ 1, sa, sb, (kk + 1) * 32);
#pragma unroll
            for (int mi = 0; mi < 4; mi++)
#pragma unroll
                for (int ni = 0; ni < 8; ni++) {
                    if (FP8) mma_fp8(acc[mi][ni], af[cur][mi], bfr[cur][ni]);
                    else     mma_bf16(acc[mi][ni], af[cur][mi], bfr[cur][ni]);
                }
        }
    }

    // ---- epilogue ----
    const float sc = __bfloat162float(__float2bfloat16(0.08838834764831845f));
#pragma unroll
    for (int mi = 0; mi < 4; mi++) {
#pragma unroll
        for (int ni = 0; ni < 8; ni++) {
            int row = wm * 64 + mi * 16 + g;
            int col = wn * 64 + ni * 8 + t4 * 2;
            size_t o0 = cofs + (size_t)row * ldc + col;
            size_t o1 = o0 + (size_t)8 * ldc;
            float a0 = acc[mi][ni][0], a1 = acc[mi][ni][1];
            float a2 = acc[mi][ni][2], a3 = acc[mi][ni][3];
            if (MODE == 0) {
                bf16* Cb = (bf16*)Cout;
                __nv_bfloat162 v0, v1;
                v0.x = __float2bfloat16(a0); v0.y = __float2bfloat16(a1);
                v1.x = __float2bfloat16(a2); v1.y = __float2bfloat16(a3);
                *(__nv_bfloat162*)(Cb + o0) = v0;
                *(__nv_bfloat162*)(Cb + o1) = v1;
            } else if (MODE == 1) {
                bf16* Cb = (bf16*)Cout;
                __nv_bfloat162 v0, v1;
                v0.x = __float2bfloat16(__bfloat162float(__float2bfloat16(a0)) * sc);
                v0.y = __float2bfloat16(__bfloat162float(__float2bfloat16(a1)) * sc);
                v1.x = __float2bfloat16(__bfloat162float(__float2bfloat16(a2)) * sc);
                v1.y = __float2bfloat16(__bfloat162float(__float2bfloat16(a3)) * sc);
                *(__nv_bfloat162*)(Cb + o0) = v0;
                *(__nv_bfloat162*)(Cb + o1) = v1;
            } else if (MODE == 2) {
                u8* C8 = (u8*)Cout;
                uint16_t w0 = (uint16_t)e4m3b(__bfloat162float(__float2bfloat16(a0)))
                            | ((uint16_t)e4m3b(__bfloat162float(__float2bfloat16(a1))) << 8);
                uint16_t w1 = (uint16_t)e4m3b(__bfloat162float(__float2bfloat16(a2)))
                            | ((uint16_t)e4m3b(__bfloat162float(__float2bfloat16(a3))) << 8);
                *(uint16_t*)(C8 + o0) = w0;
                *(uint16_t*)(C8 + o1) = w1;
            } else {
                float* Cf = (float*)Cout;
                float2 v0, v1;
                v0.x = __bfloat162float(__float2bfloat16(a0));
                v0.y = __bfloat162float(__float2bfloat16(a1));
                v1.x = __bfloat162float(__float2bfloat16(a2));
                v1.y = __bfloat162float(__float2bfloat16(a3));
                *(float2*)(Cf + o0) = v0;
                *(float2*)(Cf + o1) = v1;
            }
        }
    }
}

// ---------------- softmax: bf16 logits -> e4m3 P bytes ----------------
__global__ __launch_bounds__(256) void k_softmax() {
    __shared__ float red[8];
    size_t row = blockIdx.x;
    const bf16* p = g_S + row * (size_t)L_;
    u8* po = g_P8 + row * (size_t)L_;
    int tid = threadIdx.x, lane = tid & 31, w = tid >> 5;

    union { uint4 u; bf16 b[8]; } U;
    U.u = *(const uint4*)(p + tid * 8);
    float v[8];
#pragma unroll
    for (int j = 0; j < 8; j++) v[j] = __bfloat162float(U.b[j]);

    float m = v[0];
#pragma unroll
    for (int j = 1; j < 8; j++) m = fmaxf(m, v[j]);
#pragma unroll
    for (int s = 16; s > 0; s >>= 1) m = fmaxf(m, __shfl_xor_sync(0xffffffffu, m, s));
    if (lane == 0) red[w] = m;
    __syncthreads();
    float mv = fmaxf(fmaxf(fmaxf(red[0], red[1]), fmaxf(red[2], red[3])),
                     fmaxf(fmaxf(red[4], red[5]), fmaxf(red[6], red[7])));

    float sum = 0.f;
#pragma unroll
    for (int j = 0; j < 8; j++) { v[j] = expf(v[j] - mv); sum += v[j]; }
#pragma unroll
    for (int s = 16; s > 0; s >>= 1) sum += __shfl_xor_sync(0xffffffffu, sum, s);
    __syncthreads();
    if (lane == 0) red[w] = sum;
    __syncthreads();
    float tot = red[0] + red[1] + red[2] + red[3] + red[4] + red[5] + red[6] + red[7];

    union { uint2 u; u8 b[8]; } O;
#pragma unroll
    for (int j = 0; j < 8; j++) {
        float pj = v[j] / tot;
        bf16 hb = __float2bfloat16(pj);
        O.b[j] = e4m3b(__bfloat162float(hb));
    }
    *(uint2*)(po + tid * 8) = O.u;
}

// ---------------- launch ----------------
extern "C" void kernel_launch(void* const* d_in, const int* in_sizes, int n_in,
                              void* d_out, int out_size) {
    const float* inq  = (const float*)d_in[0];
    const float* inkv = (const float*)d_in[1];
    const float* Wq   = (const float*)d_in[2];
    const float* Wk   = (const float*)d_in[3];
    const float* Wv   = (const float*)d_in[4];
    const float* Wo   = (const float*)d_in[5];
    float* out = (float*)d_out;

    u8 *pX3, *pW8, *pVt8, *pP8, *pAO8;
    bf16 *pQKV, *pS;
    cudaGetSymbolAddress((void**)&pX3,  g_X3);
    cudaGetSymbolAddress((void**)&pW8,  g_W8);
    cudaGetSymbolAddress((void**)&pQKV, g_QKV);
    cudaGetSymbolAddress((void**)&pVt8, g_Vt8);
    cudaGetSymbolAddress((void**)&pS,   g_S);
    cudaGetSymbolAddress((void**)&pP8,  g_P8);
    cudaGetSymbolAddress((void**)&pAO8, g_AO8);
    u8*   pW3 = pW8 + 3 * (size_t)D_ * D_;
    bf16* pQ  = pQKV;                       // slot 0
    bf16* pK  = pQKV + (size_t)NTOK;        // slot 1

    const int SMEM = NSTG * PSTG;   // 165888
    cudaFuncSetAttribute(k_mm<0, true>,  cudaFuncAttributeMaxDynamicSharedMemorySize, SMEM);
    cudaFuncSetAttribute(k_mm<1, false>, cudaFuncAttributeMaxDynamicSharedMemorySize, SMEM);
    cudaFuncSetAttribute(k_mm<2, true>,  cudaFuncAttributeMaxDynamicSharedMemorySize, SMEM);
    cudaFuncSetAttribute(k_mm<3, true>,  cudaFuncAttributeMaxDynamicSharedMemorySize, SMEM);

    const int n = NTOK;
    dim3 tb(32, 8);

    // idx 0: all 4 weight quant+transpose
    k_qtrans4<<<dim3(64, 64, 4), tb>>>(Wq, Wk, Wv, Wo, pW8);
    // idx 1: input quants -> 3 slots (q, kv, kv)
    k_quant3<<<dim3(n / 4 / 256, 3), 256>>>(inq, inkv, n);
    // idx 2: merged Q/K/V projections via proven k_mm; z in [0,3): bb=0, hh=slot
    k_mm<0, true><<<dim3(D_ / 128, (B_ * L_) / 256, 3), 256, SMEM>>>(
        pX3, pW8, pQKV, D_, D_, D_, D_,
        0LL, (long long)NTOK,
        0LL, (long long)D_ * D_,
        0LL, (long long)NTOK, 3);
    // idx 3: S = (Q K^T)*scale per head  (global idx 5 -> ncu profiles THIS; control)
    k_mm<1, false><<<dim3(L_ / 128, L_ / 256, B_ * NH_), 256, SMEM>>>(
        (const u8*)pQ, (const u8*)pK, pS, HD_ * 2, D_ * 2, D_ * 2, L_,
        (long long)L_ * D_ * 2, HD_ * 2, (long long)L_ * D_ * 2, HD_ * 2,
        (long long)NH_ * L_ * L_, (long long)L_ * L_, NH_);
    // idx 4: V transpose + e4m3 requant per head
    k_vtrans8<<<dim3(L_ / 32, HD_ / 32, B_ * NH_), tb>>>();
    // idx 5: softmax -> e4m3 P
    k_softmax<<<B_ * NH_ * L_, 256>>>();
    // idx 6: O = P @ V per head (fp8)
    k_mm<2, true><<<dim3(HD_ / 128, L_ / 256, B_ * NH_), 256, SMEM>>>(
        pP8, pVt8, pAO8, L_, L_, L_, D_,
        (long long)NH_ * L_ * L_, (long long)L_ * L_,
        (long long)NH_ * HD_ * L_, (long long)HD_ * L_,
        (long long)L_ * D_, HD_, NH_);
    // idx 7: final projection, f32 store
    k_mm<3, true><<<dim3(D_ / 128, (B_ * L_) / 256, 1), 256, SMEM>>>(
        pAO8, pW3, out, D_, D_, D_, D_, 0LL, 0LL, 0LL, 0LL, 0LL, 0LL, 1);
}

// round 16
// speedup vs baseline: 1.5319x; 1.0212x over previous
#include <cuda_runtime.h>
#include <cuda_bf16.h>
#include <cuda_fp8.h>
#include <stdint.h>

typedef __nv_bfloat16 bf16;
typedef unsigned char u8;

#define B_   2
#define L_   2048
#define D_   2048
#define NH_  16
#define HD_  128
#define NTOK (B_ * L_ * D_)

// ---------------- scratch (device globals) ----------------
__device__ __align__(128) u8   g_X3  [3][NTOK];        // e4m3 inputs: q, kv, kv
__device__ __align__(128) u8   g_W8  [4][D_ * D_];     // e4m3 W^T
__device__ __align__(128) bf16 g_QKV [3][NTOK];        // Q, K, V projections (bf16)
__device__ __align__(128) u8   g_Vt8 [B_ * NH_ * HD_ * L_];
__device__ __align__(128) bf16 g_S   [(size_t)B_ * NH_ * L_ * L_];
__device__ __align__(128) u8   g_P8  [(size_t)B_ * NH_ * L_ * L_];
__device__ __align__(128) u8   g_AO8 [B_ * L_ * D_];

// ---------------- numerics ----------------
__device__ __forceinline__ u8 e4m3b(float x) {
    return (u8)__nv_cvt_float_to_fp8(x, __NV_SATFINITE, __NV_E4M3);
}

// ---------------- async copy / ldmatrix / mma ----------------
__device__ __forceinline__ uint32_t smem_u32(const void* p) {
    uint32_t a;
    asm("{ .reg .u64 t; cvta.to.shared.u64 t, %1; cvt.u32.u64 %0, t; }" : "=r"(a) : "l"(p));
    return a;
}
__device__ __forceinline__ void cp16(uint32_t s, const void* g) {
    asm volatile("cp.async.cg.shared.global [%0], [%1], 16;\n" :: "r"(s), "l"(g) : "memory");
}
__device__ __forceinline__ void cp_commit() { asm volatile("cp.async.commit_group;\n" ::: "memory"); }
template <int N>
__device__ __forceinline__ void cp_wait() { asm volatile("cp.async.wait_group %0;\n" :: "n"(N) : "memory"); }
__device__ __forceinline__ void ldm_x4(uint32_t* r, uint32_t a) {
    asm volatile("ldmatrix.sync.aligned.m8n8.x4.shared.b16 {%0,%1,%2,%3}, [%4];"
                 : "=r"(r[0]), "=r"(r[1]), "=r"(r[2]), "=r"(r[3]) : "r"(a));
}
__device__ __forceinline__ void mma_bf16(float* c, const uint32_t* a, const uint32_t* b) {
    asm volatile(
        "mma.sync.aligned.m16n8k16.row.col.f32.bf16.bf16.f32 "
        "{%0,%1,%2,%3}, {%4,%5,%6,%7}, {%8,%9}, {%0,%1,%2,%3};\n"
        : "+f"(c[0]), "+f"(c[1]), "+f"(c[2]), "+f"(c[3])
        : "r"(a[0]), "r"(a[1]), "r"(a[2]), "r"(a[3]), "r"(b[0]), "r"(b[1]));
}
__device__ __forceinline__ void mma_fp8(float* c, const uint32_t* a, const uint32_t* b) {
    asm volatile(
        "mma.sync.aligned.m16n8k32.row.col.f32.e4m3.e4m3.f32 "
        "{%0,%1,%2,%3}, {%4,%5,%6,%7}, {%8,%9}, {%0,%1,%2,%3};\n"
        : "+f"(c[0]), "+f"(c[1]), "+f"(c[2]), "+f"(c[3])
        : "r"(a[0]), "r"(a[1]), "r"(a[2]), "r"(a[3]), "r"(b[0]), "r"(b[1]));
}

// ---------------- fused elementwise kernels ----------------
__global__ __launch_bounds__(256) void k_quant3(const float* __restrict__ in0,
                                                const float* __restrict__ in1, int n) {
    const float* in = (blockIdx.y == 0) ? in0 : in1;
    u8* out = g_X3[blockIdx.y];
    int i = (blockIdx.x * 256 + threadIdx.x) * 4;
    if (i >= n) return;
    float4 v = *(const float4*)(in + i);
    uint32_t w = (uint32_t)e4m3b(v.x) | ((uint32_t)e4m3b(v.y) << 8)
               | ((uint32_t)e4m3b(v.z) << 16) | ((uint32_t)e4m3b(v.w) << 24);
    *(uint32_t*)(out + i) = w;
}

__global__ __launch_bounds__(256) void k_qtrans4(const float* __restrict__ W0,
                                                 const float* __restrict__ W1,
                                                 const float* __restrict__ W2,
                                                 const float* __restrict__ W3,
                                                 u8* __restrict__ Wt) {
    __shared__ float t[32][33];
    int zz = blockIdx.z;
    const float* W = (zz == 0) ? W0 : (zz == 1) ? W1 : (zz == 2) ? W2 : W3;
    u8* dst = Wt + (size_t)zz * D_ * D_;
    int n0 = blockIdx.x * 32, k0 = blockIdx.y * 32;
    int tx = threadIdx.x, ty0 = threadIdx.y;
#pragma unroll
    for (int j = 0; j < 4; j++) {
        int ty = ty0 + j * 8;
        t[ty][tx] = W[(size_t)(k0 + ty) * D_ + n0 + tx];
    }
    __syncthreads();
#pragma unroll
    for (int j = 0; j < 4; j++) {
        int ty = ty0 + j * 8;
        dst[(size_t)(n0 + ty) * D_ + k0 + tx] = e4m3b(t[tx][ty]);
    }
}

__global__ __launch_bounds__(256) void k_vtrans8() {
    __shared__ u8 t[32][36];
    int z = blockIdx.z; int b = z / NH_, n = z % NH_;
    int kk0 = blockIdx.x * 32, h0 = blockIdx.y * 32;
    int tx = threadIdx.x, ty0 = threadIdx.y;
#pragma unroll
    for (int j = 0; j < 4; j++) {
        int ty = ty0 + j * 8;
        bf16 v = g_QKV[2][(size_t)(b * L_ + kk0 + ty) * D_ + n * HD_ + h0 + tx];
        t[ty][tx] = e4m3b(__bfloat162float(v));
    }
    __syncthreads();
#pragma unroll
    for (int j = 0; j < 4; j++) {
        int ty = ty0 + j * 8;
        g_Vt8[((size_t)(b * NH_ + n) * HD_ + h0 + ty) * L_ + kk0 + tx] = t[tx][ty];
    }
}

// ================= unified byte-addressed NT GEMM (R7 proven-best, verbatim) =================
#define STRD  144
#define ASTG  (256 * STRD)
#define BSTG  (128 * STRD)
#define PSTG  (ASTG + BSTG)
#define NSTG  3

template <int MODE, bool FP8>
__global__ __launch_bounds__(256, 1) void k_mm(
    const u8* __restrict__ A, const u8* __restrict__ B, void* __restrict__ Cout,
    int Kb, int ldab, int ldbb, int ldc,
    long long sAb, long long sAn, long long sBb, long long sBn,
    long long sCb, long long sCn, int nh)
{
    extern __shared__ __align__(16) u8 dsm[];

    int z = blockIdx.z;
    int bb = z / nh, hh = z % nh;
    A += (size_t)bb * sAb + (size_t)hh * sAn + (size_t)blockIdx.y * 256 * ldab;
    B += (size_t)bb * sBb + (size_t)hh * sBn + (size_t)blockIdx.x * 128 * ldbb;
    size_t cofs = (size_t)bb * sCb + (size_t)hh * sCn + (size_t)blockIdx.y * 256 * ldc
                  + (size_t)blockIdx.x * 128;

    int tid = threadIdx.x;
    int warp = tid >> 5, lane = tid & 31;
    int wm = warp >> 1, wn = warp & 1;
    int g = lane >> 2, t4 = lane & 3;

    uint32_t sbase = smem_u32(dsm);
    int lr = lane & 7, h8 = (lane >> 3) & 1, q = lane >> 4;
    uint32_t aoff = (uint32_t)((wm * 64 + h8 * 8 + lr) * STRD + q * 16);
    uint32_t boff = (uint32_t)((wn * 64 + q * 8 + lr) * STRD + h8 * 16);

    float acc[4][8][4];
#pragma unroll
    for (int i = 0; i < 4; i++)
#pragma unroll
        for (int j = 0; j < 8; j++)
#pragma unroll
            for (int p = 0; p < 4; p++) acc[i][j][p] = 0.f;

    int nK = Kb / 128;
    int r8 = tid >> 3, c8 = (tid & 7) * 16;

    auto load_stage = [&](int stg, int kt) {
        const u8* Ag = A + (size_t)kt * 128;
        const u8* Bg = B + (size_t)kt * 128;
        uint32_t sa = sbase + stg * PSTG;
        uint32_t sb = sa + ASTG;
#pragma unroll
        for (int i = 0; i < 8; i++) {
            int rr = r8 + i * 32;
            cp16(sa + rr * STRD + c8, Ag + (size_t)rr * ldab + c8);
        }
#pragma unroll
        for (int i = 0; i < 4; i++) {
            int rr = r8 + i * 32;
            cp16(sb + rr * STRD + c8, Bg + (size_t)rr * ldbb + c8);
        }
        cp_commit();
    };

    load_stage(0, 0);
    if (nK > 1) load_stage(1, 1); else cp_commit();

    uint32_t af[2][4][4], bfr[2][8][2];

    auto load_frags = [&](int buf, uint32_t sa, uint32_t sb, uint32_t k0) {
#pragma unroll
        for (int mi = 0; mi < 4; mi++)
            ldm_x4(af[buf][mi], sa + aoff + mi * (16 * STRD) + k0);
#pragma unroll
        for (int nj = 0; nj < 4; nj++) {
            uint32_t qd[4];
            ldm_x4(qd, sb + boff + nj * (16 * STRD) + k0);
            bfr[buf][2 * nj][0] = qd[0]; bfr[buf][2 * nj][1] = qd[1];
            bfr[buf][2 * nj + 1][0] = qd[2]; bfr[buf][2 * nj + 1][1] = qd[3];
        }
    };

    for (int kt = 0; kt < nK; kt++) {
        cp_wait<1>();
        __syncthreads();
        if (kt + 2 < nK) load_stage((kt + 2) % NSTG, kt + 2);
        else cp_commit();

        uint32_t sa = sbase + (kt % NSTG) * PSTG;
        uint32_t sb = sa + ASTG;

        load_frags(0, sa, sb, 0);
#pragma unroll
        for (int kk = 0; kk < 4; kk++) {
            int cur = kk & 1;
            if (kk < 3) load_frags(cur ^ 1, sa, sb, (kk + 1) * 32);
#pragma unroll
            for (int mi = 0; mi < 4; mi++)
#pragma unroll
                for (int ni = 0; ni < 8; ni++) {
                    if (FP8) mma_fp8(acc[mi][ni], af[cur][mi], bfr[cur][ni]);
                    else     mma_bf16(acc[mi][ni], af[cur][mi], bfr[cur][ni]);
                }
        }
    }

    // ---- epilogue ----
#pragma unroll
    for (int mi = 0; mi < 4; mi++) {
#pragma unroll
        for (int ni = 0; ni < 8; ni++) {
            int row = wm * 64 + mi * 16 + g;
            int col = wn * 64 + ni * 8 + t4 * 2;
            size_t o0 = cofs + (size_t)row * ldc + col;
            size_t o1 = o0 + (size_t)8 * ldc;
            float a0 = acc[mi][ni][0], a1 = acc[mi][ni][1];
            float a2 = acc[mi][ni][2], a3 = acc[mi][ni][3];
            if (MODE == 0) {
                bf16* Cb = (bf16*)Cout;
                __nv_bfloat162 v0, v1;
                v0.x = __float2bfloat16(a0); v0.y = __float2bfloat16(a1);
                v1.x = __float2bfloat16(a2); v1.y = __float2bfloat16(a3);
                *(__nv_bfloat162*)(Cb + o0) = v0;
                *(__nv_bfloat162*)(Cb + o1) = v1;
            } else if (MODE == 2) {
                u8* C8 = (u8*)Cout;
                uint16_t w0 = (uint16_t)e4m3b(__bfloat162float(__float2bfloat16(a0)))
                            | ((uint16_t)e4m3b(__bfloat162float(__float2bfloat16(a1))) << 8);
                uint16_t w1 = (uint16_t)e4m3b(__bfloat162float(__float2bfloat16(a2)))
                            | ((uint16_t)e4m3b(__bfloat162float(__float2bfloat16(a3))) << 8);
                *(uint16_t*)(C8 + o0) = w0;
                *(uint16_t*)(C8 + o1) = w1;
            } else {
                float* Cf = (float*)Cout;
                float2 v0, v1;
                v0.x = __bfloat162float(__float2bfloat16(a0));
                v0.y = __bfloat162float(__float2bfloat16(a1));
                v1.x = __bfloat162float(__float2bfloat16(a2));
                v1.y = __bfloat162float(__float2bfloat16(a3));
                *(float2*)(Cf + o0) = v0;
                *(float2*)(Cf + o1) = v1;
            }
        }
    }
}

// ================= single-shot QK kernel: 128x128 tile, 2 CTAs/SM =================
// A = Q [128 x 256B], B = K [128 x 256B] per CTA; whole K-extent resident; one barrier.
// Epilogue: S = bf16( bf16(acc) * bf16(scale) ). k-slice order identical to ring kernel.
#define QSTRD 272
#define QASZ  (128 * QSTRD)
#define QSMEM (2 * QASZ)

__global__ __launch_bounds__(256, 2) void k_qk() {
    extern __shared__ __align__(16) u8 dsm[];

    int z = blockIdx.z;
    const u8* A = (const u8*)g_QKV[0]
                  + (size_t)(z / NH_) * (L_ * D_ * 2) + (size_t)(z % NH_) * (HD_ * 2)
                  + (size_t)blockIdx.y * 128 * (D_ * 2);
    const u8* B = (const u8*)g_QKV[1]
                  + (size_t)(z / NH_) * (L_ * D_ * 2) + (size_t)(z % NH_) * (HD_ * 2)
                  + (size_t)blockIdx.x * 128 * (D_ * 2);
    bf16* S = g_S + (size_t)z * L_ * L_ + (size_t)blockIdx.y * 128 * L_
              + (size_t)blockIdx.x * 128;

    int tid = threadIdx.x;
    int warp = tid >> 5, lane = tid & 31;
    int wm = warp >> 2, wn = warp & 3;       // 2x4 warps, warp tile 64x32
    int g = lane >> 2, t4 = lane & 3;

    uint32_t sa = smem_u32(dsm);
    uint32_t sb = sa + QASZ;
    int lr = lane & 7, h8 = (lane >> 3) & 1, q = lane >> 4;
    uint32_t aoff = (uint32_t)((wm * 64 + h8 * 8 + lr) * QSTRD + q * 16);
    uint32_t boff = (uint32_t)((wn * 32 + q * 8 + lr) * QSTRD + h8 * 16);

    // single load: each row is 16 chunks of 16B; 128 rows -> 2048 chunks per array
    {
        int r16 = tid >> 4, c16 = (tid & 15) * 16;
#pragma unroll
        for (int i = 0; i < 8; i++) {
            int rr = r16 + i * 16;
            cp16(sa + rr * QSTRD + c16, A + (size_t)rr * (D_ * 2) + c16);
            cp16(sb + rr * QSTRD + c16, B + (size_t)rr * (D_ * 2) + c16);
        }
        cp_commit();
        cp_wait<0>();
        __syncthreads();
    }

    float acc[4][4][4];
#pragma unroll
    for (int i = 0; i < 4; i++)
#pragma unroll
        for (int j = 0; j < 4; j++)
#pragma unroll
            for (int p = 0; p < 4; p++) acc[i][j][p] = 0.f;

#pragma unroll
    for (int kk = 0; kk < 8; kk++) {          // 8 x 32B = 256B (ascending, same order)
        uint32_t k0 = kk * 32;
        uint32_t af[4][4], bfr[4][2];
#pragma unroll
        for (int mi = 0; mi < 4; mi++)
            ldm_x4(af[mi], sa + aoff + mi * (16 * QSTRD) + k0);
#pragma unroll
        for (int nj = 0; nj < 2; nj++) {
            uint32_t qd[4];
            ldm_x4(qd, sb + boff + nj * (16 * QSTRD) + k0);
            bfr[2 * nj][0] = qd[0]; bfr[2 * nj][1] = qd[1];
            bfr[2 * nj + 1][0] = qd[2]; bfr[2 * nj + 1][1] = qd[3];
        }
#pragma unroll
        for (int mi = 0; mi < 4; mi++)
#pragma unroll
            for (int ni = 0; ni < 4; ni++)
                mma_bf16(acc[mi][ni], af[mi], bfr[ni]);
    }

    const float sc = __bfloat162float(__float2bfloat16(0.08838834764831845f));
#pragma unroll
    for (int mi = 0; mi < 4; mi++) {
#pragma unroll
        for (int ni = 0; ni < 4; ni++) {
            int row = wm * 64 + mi * 16 + g;
            int col = wn * 32 + ni * 8 + t4 * 2;
            __nv_bfloat162 v0, v1;
            v0.x = __float2bfloat16(__bfloat162float(__float2bfloat16(acc[mi][ni][0])) * sc);
            v0.y = __float2bfloat16(__bfloat162float(__float2bfloat16(acc[mi][ni][1])) * sc);
            v1.x = __float2bfloat16(__bfloat162float(__float2bfloat16(acc[mi][ni][2])) * sc);
            v1.y = __float2bfloat16(__bfloat162float(__float2bfloat16(acc[mi][ni][3])) * sc);
            *(__nv_bfloat162*)(S + (size_t)row * L_ + col)       = v0;
            *(__nv_bfloat162*)(S + (size_t)(row + 8) * L_ + col) = v1;
        }
    }
}

// ---------------- softmax: bf16 logits -> e4m3 P bytes ----------------
__global__ __launch_bounds__(256) void k_softmax() {
    __shared__ float red[8];
    size_t row = blockIdx.x;
    const bf16* p = g_S + row * (size_t)L_;
    u8* po = g_P8 + row * (size_t)L_;
    int tid = threadIdx.x, lane = tid & 31, w = tid >> 5;

    union { uint4 u; bf16 b[8]; } U;
    U.u = *(const uint4*)(p + tid * 8);
    float v[8];
#pragma unroll
    for (int j = 0; j < 8; j++) v[j] = __bfloat162float(U.b[j]);

    float m = v[0];
#pragma unroll
    for (int j = 1; j < 8; j++) m = fmaxf(m, v[j]);
#pragma unroll
    for (int s = 16; s > 0; s >>= 1) m = fmaxf(m, __shfl_xor_sync(0xffffffffu, m, s));
    if (lane == 0) red[w] = m;
    __syncthreads();
    float mv = fmaxf(fmaxf(fmaxf(red[0], red[1]), fmaxf(red[2], red[3])),
                     fmaxf(fmaxf(red[4], red[5]), fmaxf(red[6], red[7])));

    float sum = 0.f;
#pragma unroll
    for (int j = 0; j < 8; j++) { v[j] = expf(v[j] - mv); sum += v[j]; }
#pragma unroll
    for (int s = 16; s > 0; s >>= 1) sum += __shfl_xor_sync(0xffffffffu, sum, s);
    __syncthreads();
    if (lane == 0) red[w] = sum;
    __syncthreads();
    float tot = red[0] + red[1] + red[2] + red[3] + red[4] + red[5] + red[6] + red[7];

    union { uint2 u; u8 b[8]; } O;
#pragma unroll
    for (int j = 0; j < 8; j++) {
        float pj = v[j] / tot;
        bf16 hb = __float2bfloat16(pj);
        O.b[j] = e4m3b(__bfloat162float(hb));
    }
    *(uint2*)(po + tid * 8) = O.u;
}

// ---------------- launch ----------------
extern "C" void kernel_launch(void* const* d_in, const int* in_sizes, int n_in,
                              void* d_out, int out_size) {
    const float* inq  = (const float*)d_in[0];
    const float* inkv = (const float*)d_in[1];
    const float* Wq   = (const float*)d_in[2];
    const float* Wk   = (const float*)d_in[3];
    const float* Wv   = (const float*)d_in[4];
    const float* Wo   = (const float*)d_in[5];
    float* out = (float*)d_out;

    u8 *pX3, *pW8, *pVt8, *pP8, *pAO8;
    bf16 *pQKV;
    cudaGetSymbolAddress((void**)&pX3,  g_X3);
    cudaGetSymbolAddress((void**)&pW8,  g_W8);
    cudaGetSymbolAddress((void**)&pQKV, g_QKV);
    cudaGetSymbolAddress((void**)&pVt8, g_Vt8);
    cudaGetSymbolAddress((void**)&pP8,  g_P8);
    cudaGetSymbolAddress((void**)&pAO8, g_AO8);
    u8* pW3 = pW8 + 3 * (size_t)D_ * D_;

    const int SMEM = NSTG * PSTG;   // 165888
    cudaFuncSetAttribute(k_mm<0, true>, cudaFuncAttributeMaxDynamicSharedMemorySize, SMEM);
    cudaFuncSetAttribute(k_mm<2, true>, cudaFuncAttributeMaxDynamicSharedMemorySize, SMEM);
    cudaFuncSetAttribute(k_mm<3, true>, cudaFuncAttributeMaxDynamicSharedMemorySize, SMEM);
    cudaFuncSetAttribute(k_qk,          cudaFuncAttributeMaxDynamicSharedMemorySize, QSMEM);

    const int n = NTOK;
    dim3 tb(32, 8);

    // idx 0: all 4 weight quant+transpose
    k_qtrans4<<<dim3(64, 64, 4), tb>>>(Wq, Wk, Wv, Wo, pW8);
    // idx 1: input quants -> 3 slots (q, kv, kv)
    k_quant3<<<dim3(n / 4 / 256, 3), 256>>>(inq, inkv, n);
    // idx 2: merged Q/K/V projections via proven k_mm
    k_mm<0, true><<<dim3(D_ / 128, (B_ * L_) / 256, 3), 256, SMEM>>>(
        pX3, pW8, pQKV, D_, D_, D_, D_,
        0LL, (long long)NTOK,
        0LL, (long long)D_ * D_,
        0LL, (long long)NTOK, 3);
    // idx 3: S = (Q K^T)*scale per head — 2-CTA/SM single-shot kernel (profiled at global idx 5)
    k_qk<<<dim3(L_ / 128, L_ / 128, B_ * NH_), 256, QSMEM>>>();
    // idx 4: V transpose + e4m3 requant per head
    k_vtrans8<<<dim3(L_ / 32, HD_ / 32, B_ * NH_), tb>>>();
    // idx 5: softmax -> e4m3 P
    k_softmax<<<B_ * NH_ * L_, 256>>>();
    // idx 6: O = P @ V per head (fp8)
    k_mm<2, true><<<dim3(HD_ / 128, L_ / 256, B_ * NH_), 256, SMEM>>>(
        pP8, pVt8, pAO8, L_, L_, L_, D_,
        (long long)NH_ * L_ * L_, (long long)L_ * L_,
        (long long)NH_ * HD_ * L_, (long long)HD_ * L_,
        (long long)L_ * D_, HD_, NH_);
    // idx 7: final projection, f32 store
    k_mm<3, true><<<dim3(D_ / 128, (B_ * L_) / 256, 1), 256, SMEM>>>(
        pAO8, pW3, out, D_, D_, D_, D_, 0LL, 0LL, 0LL, 0LL, 0LL, 0LL, 1);
}